// round 17
// baseline (speedup 1.0000x reference)
#include <cuda_runtime.h>
#include <cuda_fp16.h>
#include <cuda_bf16.h>
#include <cstdint>

// Problem constants
#define NB   128          // batch
#define NT   64           // max timesteps
#define NE   512          // embedding dim
#define NH   1024         // hidden dim
#define N3H  3072         // 3*H (gate order r,z,n)
#define NBT  (NB*NT)      // 8192 rows for xgates GEMM

// k_recur geometry: CTA owns 32 units x 32 batch rows; 8 warps = 4 uh x 2 ks
#define UCNT   32                 // hidden units per CTA
#define BROWS  32                 // batch rows per CTA
#define SWROWS 96                 // 3 gates * 32 units
#define SWW    520                // w_hh row stride: 512 words + 8 pad
#define SHW    68                 // stage row: 32w lo-chunk + 32w hi-chunk + 4 pad
#define NSTG   3                  // cp.async ring depth
#define STGW   (BROWS * SHW)      // words per stage (2176)

// k_xgates smem geometry (128x128 tile, 2 CTAs/SM — R14 winner)
#define XAW    36                 // A row stride (LDSM conflict-free)
#define XBW    40                 // B row stride (paired LDS.64 conflict-free)
#define XASTG  (128 * XAW)        // 4608 words per A stage
#define XBSTG  (128 * XBW)        // 5120 words per B stage

// Scratch (device globals; no runtime allocation allowed)
__device__ __align__(16) __half g_xg[(size_t)NT * NB * N3H]; // [t][b][3H] fp16
__device__ __align__(16) __half g_h16[2][NB * NH];           // fp16 h exchange (L2)
__device__ __align__(16) __half g_a16[(size_t)NBT * NE];     // gathered emb, fp16
__device__ __align__(16) __half g_w16[(size_t)N3H * NE];     // w_ih fp16, PAIRED layout
__device__ float g_final[NB * NH];                           // h at t == len-1
__device__ unsigned g_qf[4][32][8];                          // [bq][ug] flags, 32B spaced

// ---------------------------------------------------------------------------
// helpers
// ---------------------------------------------------------------------------
__device__ __forceinline__ void mma_f16(float c[4], const uint32_t a[4],
                                        uint32_t b0, uint32_t b1) {
    asm volatile(
        "mma.sync.aligned.m16n8k16.row.col.f32.f16.f16.f32 "
        "{%0,%1,%2,%3}, {%4,%5,%6,%7}, {%8,%9}, {%0,%1,%2,%3};"
        : "+f"(c[0]), "+f"(c[1]), "+f"(c[2]), "+f"(c[3])
        : "r"(a[0]), "r"(a[1]), "r"(a[2]), "r"(a[3]), "r"(b0), "r"(b1));
}

__device__ __forceinline__ void ldsm_x4(uint32_t a[4], uint32_t saddr) {
    asm volatile(
        "ldmatrix.sync.aligned.m8n8.x4.shared.b16 {%0,%1,%2,%3}, [%4];"
        : "=r"(a[0]), "=r"(a[1]), "=r"(a[2]), "=r"(a[3]) : "r"(saddr));
}

__device__ __forceinline__ void cp_async16(uint32_t saddr, const void* gaddr) {
    asm volatile("cp.async.cg.shared.global [%0], [%1], 16;"
                 :: "r"(saddr), "l"(gaddr));
}
__device__ __forceinline__ void cp_commit() {
    asm volatile("cp.async.commit_group;");
}
template <int N>
__device__ __forceinline__ void cp_wait() {
    asm volatile("cp.async.wait_group %0;" :: "n"(N));
}

__device__ __forceinline__ unsigned ld_acq(const unsigned* p) {
    unsigned v;
    asm volatile("ld.acquire.gpu.global.u32 %0, [%1];" : "=r"(v) : "l"(p));
    return v;
}
__device__ __forceinline__ void st_rel(unsigned* p, unsigned v) {
    asm volatile("st.release.gpu.global.u32 [%0], %1;" :: "l"(p), "r"(v));
}

__device__ __forceinline__ uint32_t packh2(float x, float y) {
    __half2 p = __floats2half2_rn(x, y);
    return *reinterpret_cast<uint32_t*>(&p);
}

// ---------------------------------------------------------------------------
// k_cvt: gather emb rows per (b,t) token -> fp16; convert w_ih -> fp16 in
// FRAGMENT-PAIRED layout. Also (fused init): blocks <512 zero h16[0],
// block 0 zeros the flags.
// ---------------------------------------------------------------------------
__global__ void __launch_bounds__(128)
k_cvt(const int* __restrict__ sent, const float* __restrict__ emb,
      const float* __restrict__ w_ih) {
    const int row = blockIdx.x;
    const int tid = threadIdx.x;

    if (row < 512)
        reinterpret_cast<uint32_t*>(g_h16[0])[row * 128 + tid] = 0u;
    if (row == 0) {
#pragma unroll
        for (int i = 0; i < 8; i++)
            ((unsigned*)g_qf)[tid + i * 128] = 0u;
    }

    if (row < NBT) {
        const float* src = emb + (size_t)sent[row] * NE;
        __half* dst = g_a16 + (size_t)row * NE;
        const float4 v = reinterpret_cast<const float4*>(src)[tid];
        uint2 u;
        u.x = packh2(v.x, v.y);
        u.y = packh2(v.z, v.w);
        reinterpret_cast<uint2*>(dst)[tid] = u;
    } else {
        const int r = row - NBT;
        const float* src = w_ih + (size_t)r * NE;
        uint32_t* dst = reinterpret_cast<uint32_t*>(g_w16 + (size_t)r * NE);
        const int kc = tid >> 2;
        const int f  = tid & 3;
        const float4 v = reinterpret_cast<const float4*>(src + kc * 16)[f];
        uint32_t wlo = packh2(v.x, v.y);
        uint32_t whi = packh2(v.z, v.w);
        const int j0 = 2 * f, j1 = 2 * f + 1;
        const int s0 = (j0 < 4) ? (2 * j0) : (2 * (j0 - 4) + 1);
        const int s1 = (j1 < 4) ? (2 * j1) : (2 * (j1 - 4) + 1);
        dst[kc * 8 + s0] = wlo;
        dst[kc * 8 + s1] = whi;
    }
}

// ---------------------------------------------------------------------------
// k_xgates: fp16 GEMM, 128x128 tile, 2 CTAs/SM (R14 winner, UNCHANGED).
// ---------------------------------------------------------------------------
__global__ void __launch_bounds__(256, 2)
k_xgates(const float* __restrict__ b_ih) {
    extern __shared__ uint32_t xsm[];
    uint32_t* sA = xsm;                    // [2][128][XAW]
    uint32_t* sB = xsm + 2 * XASTG;        // [2][128][XBW]

    const int tid  = threadIdx.x;
    const int wid  = tid >> 5;
    const int lane = tid & 31;
    const int g    = lane >> 2;
    const int t4   = lane & 3;

    const int m0 = blockIdx.y * 128;
    const int n0 = blockIdx.x * 128;
    const int wm = (wid & 3) * 32;
    const int wn = (wid >> 2) * 64;

    int ldrow[4], ldc[4];
#pragma unroll
    for (int p = 0; p < 4; p++) {
        int idx = tid + p * 256;
        ldrow[p] = idx >> 3;
        ldc[p]   = idx & 7;
    }

    const int lm_row = (lane & 7) + ((lane >> 3) & 1) * 8;
    const int lm_wrd = ((lane >> 4) & 1) * 4;
    const uint32_t a_off0 = (uint32_t)(((wm + 0  + lm_row) * XAW + lm_wrd) * 4);
    const uint32_t a_off1 = (uint32_t)(((wm + 16 + lm_row) * XAW + lm_wrd) * 4);
    const uint32_t sa_base = (uint32_t)__cvta_generic_to_shared(sA);

    float c[2][8][4];
#pragma unroll
    for (int mf = 0; mf < 2; mf++)
#pragma unroll
        for (int nt = 0; nt < 8; nt++)
#pragma unroll
            for (int e = 0; e < 4; e++) c[mf][nt][e] = 0.0f;

#pragma unroll
    for (int p = 0; p < 4; p++) {
        uint32_t sa = (uint32_t)__cvta_generic_to_shared(
            sA + ldrow[p] * XAW + ldc[p] * 4);
        cp_async16(sa, g_a16 + (size_t)(m0 + ldrow[p]) * NE + ldc[p] * 8);
        uint32_t sb = (uint32_t)__cvta_generic_to_shared(
            sB + ldrow[p] * XBW + ldc[p] * 4);
        cp_async16(sb, g_w16 + (size_t)(n0 + ldrow[p]) * NE + ldc[p] * 8);
    }
    cp_commit();

    for (int kt = 0; kt < 8; kt++) {
        const int cur = kt & 1;
        if (kt + 1 < 8) {
            const int nxt = cur ^ 1;
            const int kk = (kt + 1) * 64;
#pragma unroll
            for (int p = 0; p < 4; p++) {
                uint32_t sa = (uint32_t)__cvta_generic_to_shared(
                    sA + nxt * XASTG + ldrow[p] * XAW + ldc[p] * 4);
                cp_async16(sa, g_a16 + (size_t)(m0 + ldrow[p]) * NE + kk + ldc[p] * 8);
                uint32_t sb = (uint32_t)__cvta_generic_to_shared(
                    sB + nxt * XBSTG + ldrow[p] * XBW + ldc[p] * 4);
                cp_async16(sb, g_w16 + (size_t)(n0 + ldrow[p]) * NE + kk + ldc[p] * 8);
            }
        }
        cp_commit();
        cp_wait<1>();
        __syncthreads();

        const uint32_t a_base = sa_base + (uint32_t)(cur * XASTG * 4);
        const uint32_t* B = sB + cur * XBSTG;
#pragma unroll
        for (int kc = 0; kc < 4; kc++) {
            uint32_t a0[4], a1[4];
            ldsm_x4(a0, a_base + a_off0 + kc * 32);
            ldsm_x4(a1, a_base + a_off1 + kc * 32);
            const int wo = kc * 8 + t4 * 2;
#pragma unroll
            for (int nt = 0; nt < 8; nt++) {
                uint2 wv = *reinterpret_cast<const uint2*>(
                    B + (wn + nt * 8 + g) * XBW + wo);
                mma_f16(c[0][nt], a0, wv.x, wv.y);
                mma_f16(c[1][nt], a1, wv.x, wv.y);
            }
        }
        __syncthreads();
    }

#pragma unroll
    for (int mf = 0; mf < 2; mf++) {
#pragma unroll
        for (int nt = 0; nt < 8; nt++) {
#pragma unroll
            for (int half = 0; half < 2; half++) {
                int m = m0 + wm + mf * 16 + g + half * 8;
                int b = m >> 6;
                int tt = m & 63;
                int n = n0 + wn + nt * 8 + (t4 << 1);
                float ox = c[mf][nt][half * 2 + 0] + __ldg(b_ih + n);
                float oy = c[mf][nt][half * 2 + 1] + __ldg(b_ih + n + 1);
                *reinterpret_cast<__half2*>(
                    &g_xg[((size_t)tt * NB + b) * N3H + n]) =
                    __floats2half2_rn(ox, oy);
            }
        }
    }
}

// ---------------------------------------------------------------------------
// k_recur: PERSISTENT GRU recurrence (R13 loop) + fused L2-norm tail, with a
// SPLIT flag wait: phase A gates the prologue on the 8 producers feeding
// stages 0,1 (ug {0-3,16-19}); phase B polls the remaining 24 flags AFTER the
// prologue cp.asyncs are in flight, so the acquire round-trip overlaps the
// stage-0 load latency instead of extending the critical path.
// ---------------------------------------------------------------------------
__global__ void __launch_bounds__(256)
k_recur(const int* __restrict__ slen, const float* __restrict__ w_hh,
        const float* __restrict__ b_hh, float* __restrict__ out) {
    extern __shared__ uint32_t sm[];
    uint32_t* sW = sm;                    // [96][SWW] fragment-paired
    uint32_t* sH = sm + SWROWS * SWW;     // [NSTG][32][SHW]; tail reused for partials

    const int tid  = threadIdx.x;
    const int wid  = tid >> 5;
    const int lane = tid & 31;
    const int g    = lane >> 2;
    const int t4   = lane & 3;

    const int ks = wid >> 2;              // K-half 0/1
    const int uh = wid & 3;               // unit octet 0..3

    const int ug = blockIdx.x >> 2;       // unit group 0..31
    const int bq = blockIdx.x & 3;        // batch quarter 0..3
    const int j0 = ug * UCNT;
    const int b0 = bq * BROWS;

    // ---- convert w_hh rows to fragment-paired fp16 smem layout (once) ----
    for (int i = tid; i < SWROWS * 64; i += 256) {
        int r  = i >> 6;
        int kc = i & 63;
        int grow = (r >> 5) * NH + j0 + (r & 31);
        const float4* src = reinterpret_cast<const float4*>(
            w_hh + (size_t)grow * NH + kc * 16);
        float4 v0 = src[0], v1 = src[1], v2 = src[2], v3 = src[3];
        uint32_t w0 = packh2(v0.x, v0.y), w1 = packh2(v0.z, v0.w);
        uint32_t w2 = packh2(v1.x, v1.y), w3 = packh2(v1.z, v1.w);
        uint32_t w4 = packh2(v2.x, v2.y), w5 = packh2(v2.z, v2.w);
        uint32_t w6 = packh2(v3.x, v3.y), w7 = packh2(v3.z, v3.w);
        uint32_t* d = sW + r * SWW + kc * 8;
        d[0] = w0; d[1] = w4;   // pair for t4=0
        d[2] = w1; d[3] = w5;   // pair for t4=1
        d[4] = w2; d[5] = w6;   // pair for t4=2
        d[6] = w3; d[7] = w7;   // pair for t4=3
    }

    // ---- per-thread constants ----
    const int ja = j0 + uh * 8 + (t4 << 1);    // hidden units ja, ja+1
    int rowg[4], lenr[4];
#pragma unroll
    for (int j = 0; j < 4; j++) {
        rowg[j] = b0 + (j >> 1) * 16 + g + (j & 1) * 8;
        lenr[j] = slen[rowg[j]] - 1;
    }
    const float bra = b_hh[ja],          brb = b_hh[ja + 1];
    const float bza = b_hh[NH + ja],     bzb = b_hh[NH + ja + 1];
    const float bna = b_hh[2 * NH + ja], bnb = b_hh[2 * NH + ja + 1];

    // W row bases for the 3 gates (word offsets)
    const int wr0 = (0 * UCNT + uh * 8 + g) * SWW;
    const int wr1 = (1 * UCNT + uh * 8 + g) * SWW;
    const int wr2 = (2 * UCNT + uh * 8 + g) * SWW;

    // ldmatrix lane offsets (within a 16-row fragment)
    const int lm_row = (lane & 7) + ((lane >> 3) & 1) * 8;
    const int lm_wrd = ((lane >> 4) & 1) * 4;
    const uint32_t a_off0 = (uint32_t)(((0 * 16 + lm_row) * SHW + ks * 32 + lm_wrd) * 4);
    const uint32_t a_off1 = (uint32_t)(((1 * 16 + lm_row) * SHW + ks * 32 + lm_wrd) * 4);

    // cp.async coordinates: 2 chunks of 16B per thread per stage
    const int ldrow = tid >> 4;           // 0..15 (+16 for second row)
    const int c16   = tid & 15;           // chunk: 0-7 lo half, 8-15 hi half
    const int sh_w  = (c16 < 8) ? (c16 * 4) : (32 + (c16 - 8) * 4);
    const int gk_c  = (c16 < 8) ? (c16 * 8) : (512 + (c16 - 8) * 8);

    // split-wait flag indices
    const int ugA = (tid & 3) + ((tid >> 2) << 4);        // tid<8 -> {0-3,16-19}
    const int ugB = (tid < 12) ? (4 + tid) : (8 + tid);   // tid<24 -> {4-15,20-31}

    // fp32 h state for ks1 threads (4 row-frags x 2 units)
    float2 hprev[4];
#pragma unroll
    for (int j = 0; j < 4; j++) hprev[j] = make_float2(0.0f, 0.0f);

    __syncthreads();   // sW ready

    for (int t = 0; t < NT; t++) {
        const __half* __restrict__ h16_in = g_h16[t & 1];
        __half* __restrict__ h16_out = g_h16[(t & 1) ^ 1];

        // ---- phase A: gate prologue on the 8 producers of stages 0,1 ----
        if (tid < 8) {
            while (ld_acq(&g_qf[bq][ugA][0]) < (unsigned)t) { }
        }
        __syncthreads();

        // ---- ks1: prefetch epilogue x-gate operands (12 half2) ----
        float2 xr[4], xz[4], xn[4];
        if (ks == 1) {
#pragma unroll
            for (int j = 0; j < 4; j++) {
                const __half* xg = g_xg + ((size_t)t * NB + rowg[j]) * N3H + ja;
                xr[j] = __half22float2(__ldg((const __half2*)(xg)));
                xz[j] = __half22float2(__ldg((const __half2*)(xg + NH)));
                xn[j] = __half22float2(__ldg((const __half2*)(xg + 2 * NH)));
            }
        }

        float c[3][2][4];
#pragma unroll
        for (int nt = 0; nt < 3; nt++)
#pragma unroll
            for (int mf = 0; mf < 2; mf++)
#pragma unroll
                for (int e = 0; e < 4; e++) c[nt][mf][e] = 0.0f;

        // ---- prologue: fill stages 0,1 (each carries lo+hi chunks) ----
#pragma unroll
        for (int s = 0; s < NSTG - 1; s++) {
            uint32_t* dst = sH + s * STGW;
#pragma unroll
            for (int p = 0; p < 2; p++) {
                int rr = ldrow + p * 16;
                uint32_t sa = (uint32_t)__cvta_generic_to_shared(
                    dst + rr * SHW + sh_w);
                cp_async16(sa, h16_in + (size_t)(b0 + rr) * NH + s * 64 + gk_c);
            }
            cp_commit();
        }

        // ---- phase B: remaining 24 producers; overlaps stage-0 load flight ----
        if (tid < 24) {
            while (ld_acq(&g_qf[bq][ugB][0]) < (unsigned)t) { }
        }

        // ---- 8 stages; every warp computes its K-half chunk each stage ----
        for (int it = 0; it < 8; it++) {
            cp_wait<1>();
            __syncthreads();

            const int nxt = it + 2;
            if (nxt < 8) {
                uint32_t* dst = sH + (nxt % NSTG) * STGW;
#pragma unroll
                for (int p = 0; p < 2; p++) {
                    int rr = ldrow + p * 16;
                    uint32_t sa = (uint32_t)__cvta_generic_to_shared(
                        dst + rr * SHW + sh_w);
                    cp_async16(sa, h16_in + (size_t)(b0 + rr) * NH + nxt * 64 + gk_c);
                }
            }
            cp_commit();               // empty group in tail keeps FIFO aligned

            const uint32_t a_base = (uint32_t)__cvta_generic_to_shared(
                sH + (it % NSTG) * STGW);
#pragma unroll
            for (int kc = 0; kc < 4; kc++) {
                uint32_t a0[4], a1[4];
                ldsm_x4(a0, a_base + a_off0 + kc * 32);
                ldsm_x4(a1, a_base + a_off1 + kc * 32);
                const int wo = ((ks * 32 + it * 4 + kc) << 3) + (t4 << 1);
                uint2 wv0 = *reinterpret_cast<const uint2*>(sW + wr0 + wo);
                uint2 wv1 = *reinterpret_cast<const uint2*>(sW + wr1 + wo);
                uint2 wv2 = *reinterpret_cast<const uint2*>(sW + wr2 + wo);
                mma_f16(c[0][0], a0, wv0.x, wv0.y);
                mma_f16(c[0][1], a1, wv0.x, wv0.y);
                mma_f16(c[1][0], a0, wv1.x, wv1.y);
                mma_f16(c[1][1], a1, wv1.x, wv1.y);
                mma_f16(c[2][0], a0, wv2.x, wv2.y);
                mma_f16(c[2][1], a1, wv2.x, wv2.y);
            }
        }

        // ---- K-split reduction through the sH ring (free after last stage) ----
        __syncthreads();               // all stage reads done
        float* sP = (float*)sH;        // [6 frags][128 threads][4]
        const int pth = uh * 32 + lane;
        if (ks == 0) {
#pragma unroll
            for (int nt = 0; nt < 3; nt++)
#pragma unroll
                for (int mf = 0; mf < 2; mf++) {
                    *reinterpret_cast<float4*>(
                        sP + ((nt * 2 + mf) * 128 + pth) * 4) =
                        make_float4(c[nt][mf][0], c[nt][mf][1],
                                    c[nt][mf][2], c[nt][mf][3]);
                }
        }
        __syncthreads();

        // ---- ks1: fold partials + fused GRU gate epilogue ----
        if (ks == 1) {
#pragma unroll
            for (int nt = 0; nt < 3; nt++)
#pragma unroll
                for (int mf = 0; mf < 2; mf++) {
                    float4 v = *reinterpret_cast<const float4*>(
                        sP + ((nt * 2 + mf) * 128 + pth) * 4);
                    c[nt][mf][0] += v.x; c[nt][mf][1] += v.y;
                    c[nt][mf][2] += v.z; c[nt][mf][3] += v.w;
                }
#pragma unroll
            for (int j = 0; j < 4; j++) {
                const int mf = j >> 1;
                const int rh = j & 1;
                float hn2[2];
#pragma unroll
                for (int sub = 0; sub < 2; sub++) {
                    const int e = rh * 2 + sub;
                    float xrv = sub ? xr[j].y : xr[j].x;
                    float xzv = sub ? xz[j].y : xz[j].x;
                    float xnv = sub ? xn[j].y : xn[j].x;
                    float hov = sub ? hprev[j].y : hprev[j].x;
                    float hr = c[0][mf][e] + (sub ? brb : bra);
                    float hz = c[1][mf][e] + (sub ? bzb : bza);
                    float hh = c[2][mf][e] + (sub ? bnb : bna);
                    float rr = 1.0f / (1.0f + expf(-(xrv + hr)));
                    float zz = 1.0f / (1.0f + expf(-(xzv + hz)));
                    float nn = tanhf(xnv + rr * hh);
                    hn2[sub] = (1.0f - zz) * nn + zz * hov;
                }
                hprev[j] = make_float2(hn2[0], hn2[1]);
                __stcg((__half2*)(h16_out + (size_t)rowg[j] * NH + ja),
                       __floats2half2_rn(hn2[0], hn2[1]));
                if (lenr[j] == t)
                    *(float2*)(g_final + (size_t)rowg[j] * NH + ja) =
                        make_float2(hn2[0], hn2[1]);
            }
        }

        // ---- publish: barrier orders all threads' stores before the release ----
        __syncthreads();
        if (tid == 0) st_rel(&g_qf[bq][ug][0], (unsigned)(t + 1));
    }

    // ---- fused L2-norm tail: CTA (ug,bq) normalizes row b0+ug into out ----
    {
        if (tid < 32) {
            while (ld_acq(&g_qf[bq][tid][0]) < (unsigned)NT) { }
        }
        __syncthreads();   // all g_final writes for this quarter visible

        const int row = b0 + ug;
        const float4 v = reinterpret_cast<const float4*>(
            g_final + (size_t)row * NH)[tid];
        float s = v.x * v.x + v.y * v.y + v.z * v.z + v.w * v.w;
#pragma unroll
        for (int o = 16; o; o >>= 1) s += __shfl_xor_sync(0xFFFFFFFFu, s, o);
        float* red = (float*)sm;
        if (lane == 0) red[wid] = s;
        __syncthreads();
        if (tid == 0) {
            float x = 0.0f;
#pragma unroll
            for (int i = 0; i < 8; i++) x += red[i];
            red[8] = 1.0f / sqrtf(x);
        }
        __syncthreads();
        const float inv = red[8];
        reinterpret_cast<float4*>(out + (size_t)row * NH)[tid] =
            make_float4(v.x * inv, v.y * inv, v.z * inv, v.w * inv);
    }
}

// ---------------------------------------------------------------------------
// entry point
// ---------------------------------------------------------------------------
extern "C" void kernel_launch(void* const* d_in, const int* in_sizes, int n_in,
                              void* d_out, int out_size) {
    const int*   sent  = (const int*)d_in[0];
    const int*   slen  = (const int*)d_in[1];
    const float* emb   = (const float*)d_in[2];
    const float* w_ih  = (const float*)d_in[3];
    const float* w_hh  = (const float*)d_in[4];
    const float* b_ih  = (const float*)d_in[5];
    const float* b_hh  = (const float*)d_in[6];

    const int smem_xg    = (2 * XASTG + 2 * XBSTG) * 4;             // 77,824 B
    const int smem_recur = (SWROWS * SWW + NSTG * STGW) * 4;        // 225,792 B
    cudaFuncSetAttribute(k_xgates, cudaFuncAttributeMaxDynamicSharedMemorySize,
                         smem_xg);
    cudaFuncSetAttribute(k_recur, cudaFuncAttributeMaxDynamicSharedMemorySize,
                         smem_recur);

    k_cvt<<<NBT + N3H, 128>>>(sent, emb, w_ih);
    k_xgates<<<dim3(N3H / 128, NBT / 128), 256, smem_xg>>>(b_ih);
    k_recur<<<128, 256, smem_recur>>>(slen, w_hh, b_hh, (float*)d_out);
}